// round 1
// baseline (speedup 1.0000x reference)
#include <cuda_runtime.h>
#include <stdint.h>

#define MAX_DELAY 40000
#define T_LEN 1000000
// rows = BATCH * CHANNELS = 16
#define N_ROWS 16

// One thread handles 4 consecutive t (float4 on dt and y).
// Taps are scalar gathers into (buffer ‖ x) logical row.
__global__ __launch_bounds__(256) void tvdl_kernel(
    const float* __restrict__ x,      // (rows, T)
    const float* __restrict__ dt,     // (rows, T)
    const float* __restrict__ buf,    // (rows, MAX_DELAY)
    float* __restrict__ y)            // (rows, T)
{
    const long long n_vec = (long long)N_ROWS * (T_LEN / 4);   // 4M float4's
    long long v = blockIdx.x * (long long)blockDim.x + threadIdx.x;
    const long long stride = (long long)gridDim.x * blockDim.x;

    for (; v < n_vec; v += stride) {
        const int vec_per_row = T_LEN / 4;
        const int row = (int)(v / vec_per_row);
        const int tv  = (int)(v % vec_per_row);
        const int t0  = tv * 4;

        const float* xrow = x   + (long long)row * T_LEN;
        const float* brow = buf + (long long)row * MAX_DELAY;

        const float4 d4 = __ldg((const float4*)(dt + (long long)row * T_LEN + t0));

        float out[4];
        const float dv[4] = {d4.x, d4.y, d4.z, d4.w};

        #pragma unroll
        for (int k = 0; k < 4; ++k) {
            const int t = t0 + k;
            const float dtv = dv[k];
            const int i0 = (int)dtv;              // dtv >= 0 -> trunc == floor
            const float frac = dtv - (float)i0;

            // index into logical x_pad row of length MAX_DELAY + T
            const int idx0 = MAX_DELAY + t - i0;  // >= 2 given dt < MAX_DELAY-1
            const int idx1 = max(idx0 - 1, 0);

            float tap0, tap1;
            if (idx0 >= MAX_DELAY) tap0 = __ldg(xrow + (idx0 - MAX_DELAY));
            else                   tap0 = __ldg(brow + idx0);
            if (idx1 >= MAX_DELAY) tap1 = __ldg(xrow + (idx1 - MAX_DELAY));
            else                   tap1 = __ldg(brow + idx1);

            out[k] = (1.0f - frac) * tap0 + frac * tap1;
        }

        float4 o4 = make_float4(out[0], out[1], out[2], out[3]);
        *((float4*)(y + (long long)row * T_LEN + t0)) = o4;
    }
}

extern "C" void kernel_launch(void* const* d_in, const int* in_sizes, int n_in,
                              void* d_out, int out_size) {
    const float* x   = (const float*)d_in[0];
    const float* dt  = (const float*)d_in[1];
    const float* buf = (const float*)d_in[2];
    float* y = (float*)d_out;

    // 16M elements / 4 per thread = 4M threads. Use a grid that fills the chip
    // with a modest grid-stride loop for scheduling flexibility.
    const long long n_vec = (long long)N_ROWS * (T_LEN / 4);
    int threads = 256;
    long long blocks_ll = (n_vec + threads - 1) / threads;
    int blocks = (blocks_ll > 65536) ? 65536 : (int)blocks_ll;

    tvdl_kernel<<<blocks, threads>>>(x, dt, buf, y);
}

// round 3
// speedup vs baseline: 1.0289x; 1.0289x over previous
#include <cuda_runtime.h>
#include <stdint.h>

#define MAX_DELAY 40000
#define T_LEN 1000000
#define N_ROWS 16   // BATCH * CHANNELS

// One thread handles 4 consecutive t (float4 on dt and y).
// Tap pair (idx0, idx0-1) fetched with ONE aligned float4 gather covering the
// quad of idx0; a predicated scalar fixup covers the 25% case idx0%4==0 where
// idx0-1 falls in the previous quad. This cuts L1 wavefronts/element ~2.0->1.25.
__global__ __launch_bounds__(256) void tvdl_kernel(
    const float* __restrict__ x,      // (rows, T)
    const float* __restrict__ dt,     // (rows, T)
    const float* __restrict__ buf,    // (rows, MAX_DELAY)
    float* __restrict__ y)            // (rows, T)
{
    const int vec_per_row = T_LEN / 4;
    const long long n_vec = (long long)N_ROWS * vec_per_row;
    long long v = blockIdx.x * (long long)blockDim.x + threadIdx.x;
    const long long stride = (long long)gridDim.x * blockDim.x;

    for (; v < n_vec; v += stride) {
        const int row = (int)(v / vec_per_row);
        const int tv  = (int)(v % vec_per_row);
        const int t0  = tv * 4;

        const float* xrow = x   + (long long)row * T_LEN;
        const float* brow = buf + (long long)row * MAX_DELAY;

        const float4 d4 = __ldg((const float4*)(dt + (long long)row * T_LEN + t0));

        float out[4];
        const float dv[4] = {d4.x, d4.y, d4.z, d4.w};

        #pragma unroll
        for (int k = 0; k < 4; ++k) {
            const int t = t0 + k;
            const float dtv = dv[k];
            const int i0 = (int)dtv;              // dt >= 0 -> trunc == floor
            const float frac = dtv - (float)i0;

            // logical index into x_pad = (buf ‖ x), length MAX_DELAY + T
            const int idx0 = MAX_DELAY + t - i0;  // >= 2 always
            const int r    = idx0 & 3;
            const int q    = idx0 & ~3;           // aligned quad base

            // MAX_DELAY % 4 == 0 -> a quad is entirely in one region
            const float* qp = (q >= MAX_DELAY) ? (xrow + (q - MAX_DELAY))
                                               : (brow + q);
            const float4 g = __ldg((const float4*)qp);

            // tap0 = x_pad[idx0] = g[r]   (SEL chain, no dynamic indexing)
            const float tap0 = (r == 0) ? g.x : (r == 1) ? g.y
                             : (r == 2) ? g.z : g.w;

            // tap1 = x_pad[idx0-1]; in-quad unless r==0
            float tap1 = (r == 1) ? g.x : (r == 2) ? g.y : g.z;
            if (r == 0) {
                const int j = idx0 - 1;           // >= 1
                const float* fp = (j >= MAX_DELAY) ? (xrow + (j - MAX_DELAY))
                                                   : (brow + j);
                tap1 = __ldg(fp);                 // predicated @P LDG
            }

            // (1-f)*a + f*b  ==  a + f*(b-a)   (FADD + FFMA)
            out[k] = tap0 + frac * (tap1 - tap0);
        }

        float4 o4 = make_float4(out[0], out[1], out[2], out[3]);
        *((float4*)(y + (long long)row * T_LEN + t0)) = o4;
    }
}

extern "C" void kernel_launch(void* const* d_in, const int* in_sizes, int n_in,
                              void* d_out, int out_size) {
    const float* x   = (const float*)d_in[0];
    const float* dt  = (const float*)d_in[1];
    const float* buf = (const float*)d_in[2];
    float* y = (float*)d_out;

    const long long n_vec = (long long)N_ROWS * (T_LEN / 4);
    int threads = 256;
    long long blocks_ll = (n_vec + threads - 1) / threads;
    int blocks = (blocks_ll > 65536) ? 65536 : (int)blocks_ll;

    tvdl_kernel<<<blocks, threads>>>(x, dt, buf, y);
}

// round 6
// speedup vs baseline: 1.5019x; 1.4597x over previous
#include <cuda_runtime.h>
#include <stdint.h>

#define MAX_DELAY 40000
#define T_LEN     1000000
#define N_ROWS    16          // BATCH * CHANNELS
#define SEGS      9           // segments per row -> 16*9 = 144 blocks (<=148 SMs)
#define CHUNK     8192        // t samples per chunk
#define CAP       49152       // ring capacity (floats); CAP >= MAX_DELAY + CHUNK (+slack)
#define NTHREADS  1024
#define SMEM_BYTES (CAP * 4)  // 192 KB

// One CTA per SM, each owns a contiguous t-segment of one row.
// Sliding gather window lives in a circular smem buffer; taps are LDS gathers
// (bank-conflict cost ~3.4 cyc/warp vs ~32 L1 wavefronts for scattered LDG).
__global__ __launch_bounds__(NTHREADS, 1) void tvdl_smem_kernel(
    const float* __restrict__ x,      // (rows, T)
    const float* __restrict__ dt,     // (rows, T)
    const float* __restrict__ buf,    // (rows, MAX_DELAY)
    float* __restrict__ y)            // (rows, T)
{
    extern __shared__ float ring[];   // CAP floats

    const int bid = blockIdx.x;
    const int row = bid / SEGS;
    const int seg = bid % SEGS;
    const int tid = threadIdx.x;

    const int n_chunks = (T_LEN + CHUNK - 1) / CHUNK;         // 123
    const int chunks_per_seg = (n_chunks + SEGS - 1) / SEGS;  // 14
    const int c_begin = seg * chunks_per_seg;
    const int c_end   = min(n_chunks, c_begin + chunks_per_seg);
    if (c_begin >= c_end) return;

    const float* xrow  = x   + (long long)row * T_LEN;
    const float* dtrow = dt  + (long long)row * T_LEN;
    const float* brow  = buf + (long long)row * MAX_DELAY;
    float*       yrow  = y   + (long long)row * T_LEN;

    const int ts = c_begin * CHUNK;   // first t of this segment

    // ---- Prologue: load history window, x_pad positions [ts, ts + MAX_DELAY) ----
    // x_pad[p] = p < MAX_DELAY ? buf[p] : x[p - MAX_DELAY]
    for (int i = tid; i < MAX_DELAY; i += NTHREADS) {
        const int p = ts + i;
        const float v = (p < MAX_DELAY) ? __ldg(brow + p)
                                        : __ldg(xrow + (p - MAX_DELAY));
        ring[p % CAP] = v;
    }

    // ---- Chunk loop ----
    for (int c = c_begin; c < c_end; ++c) {
        const int t0   = c * CHUNK;
        const int t_hi = min(t0 + CHUNK, T_LEN);

        // Load the new samples x[t0..t_hi) into ring slots (MAX_DELAY + t) % CAP.
        // t multiples of 4, CAP % 4 == 0 -> slot 16B-aligned, no intra-quad wrap.
        for (int tt = t0 + tid * 4; tt < t_hi; tt += NTHREADS * 4) {
            const float4 v4 = __ldg((const float4*)(xrow + tt));
            const int slot = (MAX_DELAY + tt) % CAP;
            *((float4*)(ring + slot)) = v4;
        }
        __syncthreads();   // window complete (also covers prologue on first iter)

        // Gather + lerp + store for t in [t0, t_hi)
        for (int tt = t0 + tid * 4; tt < t_hi; tt += NTHREADS * 4) {
            const float4 d4 = __ldg((const float4*)(dtrow + tt));
            const float dv[4] = {d4.x, d4.y, d4.z, d4.w};
            float out[4];

            #pragma unroll
            for (int k = 0; k < 4; ++k) {
                const float dtv = dv[k];
                const int   i0   = (int)dtv;            // dt >= 0 -> trunc == floor
                const float frac = dtv - (float)i0;

                const int idx0 = MAX_DELAY + (tt + k) - i0;  // >= t+2 always
                int s0 = idx0 % CAP;
                int s1 = s0 - 1;
                if (s1 < 0) s1 += CAP;

                const float tap0 = ring[s0];
                const float tap1 = ring[s1];
                out[k] = tap0 + frac * (tap1 - tap0);   // (1-f)a + f b
            }

            *((float4*)(yrow + tt)) = make_float4(out[0], out[1], out[2], out[3]);
        }
        __syncthreads();   // don't overwrite slots still being gathered
    }
}

extern "C" void kernel_launch(void* const* d_in, const int* in_sizes, int n_in,
                              void* d_out, int out_size) {
    const float* x   = (const float*)d_in[0];
    const float* dt  = (const float*)d_in[1];
    const float* buf = (const float*)d_in[2];
    float* y = (float*)d_out;

    cudaFuncSetAttribute(tvdl_smem_kernel,
                         cudaFuncAttributeMaxDynamicSharedMemorySize, SMEM_BYTES);

    tvdl_smem_kernel<<<N_ROWS * SEGS, NTHREADS, SMEM_BYTES>>>(x, dt, buf, y);
}

// round 9
// speedup vs baseline: 1.9130x; 1.2738x over previous
#include <cuda_runtime.h>
#include <stdint.h>

#define MAX_DELAY 40000
#define T_LEN     1000000
#define N_ROWS    16          // BATCH * CHANNELS
#define SEGS      9           // 16*9 = 144 CTAs (one wave on 148 SMs)
#define CHUNK     4096        // samples per chunk = NTHREADS*4 (straight-line body)
#define CAP       49152       // ring floats; >= MAX_DELAY + 2*CHUNK (double-buffer slack)
#define NTHREADS  1024
#define SMEM_BYTES (CAP * 4)  // 192 KB

// Software-pipelined smem-ring delay line:
//  - sliding 40000-sample window in a circular smem buffer (LDS gathers)
//  - one barrier per chunk; next-chunk x STS overlaps current gathers
//    (write residues t0+[44096,48192) vs read residues t0+[0,44096) — disjoint)
//  - dt prefetched 1 chunk ahead, x prefetched 2 chunks ahead, in registers
__global__ __launch_bounds__(NTHREADS, 1) void tvdl_pipe_kernel(
    const float* __restrict__ x,      // (rows, T)
    const float* __restrict__ dt,     // (rows, T)
    const float* __restrict__ buf,    // (rows, MAX_DELAY)
    float* __restrict__ y)            // (rows, T)
{
    extern __shared__ float ring[];   // CAP floats

    const int bid = blockIdx.x;
    const int row = bid / SEGS;
    const int seg = bid % SEGS;
    const int tid = threadIdx.x;

    const int n_chunks = (T_LEN + CHUNK - 1) / CHUNK;   // 245
    const int base     = n_chunks / SEGS;               // 27
    const int rem      = n_chunks % SEGS;               // 2
    const int c_begin  = seg * base + min(seg, rem);
    const int c_end    = c_begin + base + (seg < rem ? 1 : 0);

    const float* xrow  = x   + (long long)row * T_LEN;
    const float* dtrow = dt  + (long long)row * T_LEN;
    const float* brow  = buf + (long long)row * MAX_DELAY;
    float*       yrow  = y   + (long long)row * T_LEN;

    const int ts = c_begin * CHUNK;      // first t of this segment (mult of 4096)
    const int off = tid * 4;             // this thread's fixed in-chunk offset

    // ---- Prologue ----
    // history: x_pad positions [ts, ts+MAX_DELAY); MAX_DELAY%4==0 -> quad on one side
    for (int i = off; i < MAX_DELAY; i += NTHREADS * 4) {
        const int p = ts + i;            // multiple of 4
        float4 v;
        if (p < MAX_DELAY) v = __ldg((const float4*)(brow + p));
        else               v = __ldg((const float4*)(xrow + (p - MAX_DELAY)));
        *((float4*)(ring + (p % CAP))) = v;
    }
    // x of first chunk into ring
    {
        const int t = ts + off;
        if (t < T_LEN) {
            const float4 v = __ldg((const float4*)(xrow + t));
            *((float4*)(ring + ((MAX_DELAY + t) % CAP))) = v;
        }
    }
    // prefetch dt(chunk c_begin) and x(chunk c_begin+1) into regs
    float4 dt_cur = make_float4(0.f, 0.f, 0.f, 0.f);
    float4 x_nxt  = make_float4(0.f, 0.f, 0.f, 0.f);
    {
        const int t = ts + off;
        if (t < T_LEN) dt_cur = __ldg((const float4*)(dtrow + t));
        const int tn = ts + CHUNK + off;
        if (tn < T_LEN) x_nxt = __ldg((const float4*)(xrow + tn));
    }
    __syncthreads();

    // ---- Chunk loop: one barrier per chunk, all LDG latency hidden ----
    for (int c = c_begin; c < c_end; ++c) {
        const int t0   = c * CHUNK;
        const int tcur = t0 + off;

        // prefetch dt for chunk c+1, x for chunk c+2
        float4 dt_nxt = make_float4(0.f, 0.f, 0.f, 0.f);
        float4 x_n2   = make_float4(0.f, 0.f, 0.f, 0.f);
        if (c + 1 < c_end) {
            const int tn = t0 + CHUNK + off;
            if (tn < T_LEN) dt_nxt = __ldg((const float4*)(dtrow + tn));
        }
        if (c + 2 < c_end) {
            const int tx = t0 + 2 * CHUNK + off;
            if (tx < T_LEN) x_n2 = __ldg((const float4*)(xrow + tx));
        }

        // gather + lerp + store (uses dt_cur loaded a full chunk ago)
        if (tcur < T_LEN) {
            const float dv[4] = {dt_cur.x, dt_cur.y, dt_cur.z, dt_cur.w};
            float out[4];
            #pragma unroll
            for (int k = 0; k < 4; ++k) {
                const float dtv  = dv[k];
                const int   i0   = (int)dtv;           // dt>=0 -> trunc==floor
                const float frac = dtv - (float)i0;
                const int idx0 = MAX_DELAY + (tcur + k) - i0;   // >= t0+1
                int s0 = idx0 % CAP;
                int s1 = s0 - 1; if (s1 < 0) s1 += CAP;
                const float tap0 = ring[s0];
                const float tap1 = ring[s1];
                out[k] = tap0 + frac * (tap1 - tap0);  // (1-f)a + f b
            }
            *((float4*)(yrow + tcur)) =
                make_float4(out[0], out[1], out[2], out[3]);
        }

        // extend window with chunk c+1's x (regs loaded last iteration);
        // write slots are disjoint from this chunk's read slots (see header)
        if (c + 1 < c_end) {
            const int tw = t0 + CHUNK + off;
            if (tw < T_LEN)
                *((float4*)(ring + ((MAX_DELAY + tw) % CAP))) = x_nxt;
        }

        __syncthreads();       // chunk c+1 window complete; gathers of c done
        dt_cur = dt_nxt;
        x_nxt  = x_n2;
    }
}

extern "C" void kernel_launch(void* const* d_in, const int* in_sizes, int n_in,
                              void* d_out, int out_size) {
    const float* x   = (const float*)d_in[0];
    const float* dt  = (const float*)d_in[1];
    const float* buf = (const float*)d_in[2];
    float* y = (float*)d_out;

    cudaFuncSetAttribute(tvdl_pipe_kernel,
                         cudaFuncAttributeMaxDynamicSharedMemorySize, SMEM_BYTES);

    tvdl_pipe_kernel<<<N_ROWS * SEGS, NTHREADS, SMEM_BYTES>>>(x, dt, buf, y);
}